// round 1
// baseline (speedup 1.0000x reference)
#include <cuda_runtime.h>
#include <cstdint>

#define BB 32
#define NN 2048
#define MM 2048
#define DD 128

#define TI 128
#define TJ 128
#define TK 16
#define ASTRIDE 132   // 128 + 4 pad, keeps 16B alignment (132*4=528 = 33*16)

// Scratch (allocation-free rule: __device__ globals)
__device__ float        g_xn[BB * NN];        // ||x_i||^2
__device__ float        g_yn[BB * MM];        // ||y_j||^2
__device__ unsigned int g_rowMin[BB * NN];    // min_j dist^2, fp32 bits (nonneg)
__device__ unsigned int g_colMin[BB * MM];    // min_i dist^2, fp32 bits (nonneg)
__device__ float        g_partial[256];

__device__ __forceinline__ float finf() { return __int_as_float(0x7f800000); }

// ---------------------------------------------------------------------------
// Kernel 0: init minima to +inf
// ---------------------------------------------------------------------------
__global__ void init_mins_kernel() {
    int i = blockIdx.x * blockDim.x + threadIdx.x;   // 0 .. 65535
    if (i < BB * NN) g_rowMin[i] = 0x7f800000u;
    if (i < BB * MM) g_colMin[i] = 0x7f800000u;
}

// ---------------------------------------------------------------------------
// Kernel 1: squared norms. One warp per row, float4 loads, shfl reduce.
// warps [0, 65536) -> x rows, [65536, 131072) -> y rows
// ---------------------------------------------------------------------------
__global__ void sqnorm_kernel(const float* __restrict__ x,
                              const float* __restrict__ y) {
    int w    = (blockIdx.x * blockDim.x + threadIdx.x) >> 5;
    int lane = threadIdx.x & 31;
    const int rowsX = BB * NN;
    const float* src;
    float* dst;
    if (w < rowsX) {
        src = x + (size_t)w * DD;
        dst = &g_xn[w];
    } else {
        int w2 = w - rowsX;
        src = y + (size_t)w2 * DD;
        dst = &g_yn[w2];
    }
    float4 v = *(const float4*)(src + lane * 4);
    float s = v.x * v.x + v.y * v.y + v.z * v.z + v.w * v.w;
    #pragma unroll
    for (int off = 16; off > 0; off >>= 1)
        s += __shfl_xor_sync(0xffffffffu, s, off);
    if (lane == 0) *dst = s;
}

// ---------------------------------------------------------------------------
// Kernel 2: main. Block = 256 thr, 128x128 tile, 8x8/thread.
// Grid (16 i-tiles, 32 batches). Each block sweeps all j-tiles.
// ---------------------------------------------------------------------------
__global__ __launch_bounds__(256, 2)
void chamfer_main_kernel(const float* __restrict__ x,
                         const float* __restrict__ y) {
    __shared__ float As[TK][ASTRIDE];
    __shared__ float Bs[TK][ASTRIDE];
    __shared__ float red[16 * 128];

    const int b   = blockIdx.y;
    const int i0  = blockIdx.x * TI;
    const int tid = threadIdx.x;
    const int tx  = tid & 15;      // col group (8 cols)
    const int ty  = tid >> 4;      // row group (8 rows)

    const float* xb = x + (size_t)b * NN * DD;
    const float* yb = y + (size_t)b * MM * DD;

    // tile-load mapping: 2 threads per row, 8 floats each
    const int li = tid >> 1;          // 0..127
    const int lk = (tid & 1) * 8;     // 0 or 8

    float xn8[8];
    #pragma unroll
    for (int r = 0; r < 8; r++)
        xn8[r] = g_xn[b * NN + i0 + ty * 8 + r];

    float rm[8];
    #pragma unroll
    for (int r = 0; r < 8; r++) rm[r] = finf();

    for (int j0 = 0; j0 < MM; j0 += TJ) {
        float acc[8][8];
        #pragma unroll
        for (int r = 0; r < 8; r++)
            #pragma unroll
            for (int c = 0; c < 8; c++) acc[r][c] = 0.0f;

        for (int k0 = 0; k0 < DD; k0 += TK) {
            __syncthreads();
            // load x tile transposed: As[k][i]
            const float* ap = xb + (size_t)(i0 + li) * DD + k0 + lk;
            float4 a0 = *(const float4*)ap;
            float4 a1 = *(const float4*)(ap + 4);
            As[lk + 0][li] = a0.x; As[lk + 1][li] = a0.y;
            As[lk + 2][li] = a0.z; As[lk + 3][li] = a0.w;
            As[lk + 4][li] = a1.x; As[lk + 5][li] = a1.y;
            As[lk + 6][li] = a1.z; As[lk + 7][li] = a1.w;
            // load y tile transposed: Bs[k][j]
            const float* bp = yb + (size_t)(j0 + li) * DD + k0 + lk;
            float4 b0 = *(const float4*)bp;
            float4 b1 = *(const float4*)(bp + 4);
            Bs[lk + 0][li] = b0.x; Bs[lk + 1][li] = b0.y;
            Bs[lk + 2][li] = b0.z; Bs[lk + 3][li] = b0.w;
            Bs[lk + 4][li] = b1.x; Bs[lk + 5][li] = b1.y;
            Bs[lk + 6][li] = b1.z; Bs[lk + 7][li] = b1.w;
            __syncthreads();

            #pragma unroll
            for (int kk = 0; kk < TK; kk++) {
                float av[8], bv[8];
                float4 t;
                t = *(const float4*)&As[kk][ty * 8];
                av[0] = t.x; av[1] = t.y; av[2] = t.z; av[3] = t.w;
                t = *(const float4*)&As[kk][ty * 8 + 4];
                av[4] = t.x; av[5] = t.y; av[6] = t.z; av[7] = t.w;
                t = *(const float4*)&Bs[kk][tx * 8];
                bv[0] = t.x; bv[1] = t.y; bv[2] = t.z; bv[3] = t.w;
                t = *(const float4*)&Bs[kk][tx * 8 + 4];
                bv[4] = t.x; bv[5] = t.y; bv[6] = t.z; bv[7] = t.w;
                #pragma unroll
                for (int r = 0; r < 8; r++)
                    #pragma unroll
                    for (int c = 0; c < 8; c++)
                        acc[r][c] = fmaf(av[r], bv[c], acc[r][c]);
            }
        }

        // ---- epilogue: sq = xn + yn - 2*acc ; fused min ----
        float yn8[8];
        #pragma unroll
        for (int c = 0; c < 8; c++)
            yn8[c] = g_yn[b * MM + j0 + tx * 8 + c];

        float cm[8];
        #pragma unroll
        for (int c = 0; c < 8; c++) cm[c] = finf();

        #pragma unroll
        for (int r = 0; r < 8; r++) {
            #pragma unroll
            for (int c = 0; c < 8; c++) {
                float sq = fmaf(-2.0f, acc[r][c], xn8[r] + yn8[c]);
                rm[r] = fminf(rm[r], sq);
                cm[c] = fminf(cm[c], sq);
            }
        }

        __syncthreads();   // prior red readers done
        #pragma unroll
        for (int c = 0; c < 8; c++)
            red[ty * 128 + tx * 8 + c] = cm[c];
        __syncthreads();

        if (tid < 128) {
            float m = finf();
            #pragma unroll
            for (int t = 0; t < 16; t++)
                m = fminf(m, red[t * 128 + tid]);
            m = fmaxf(m, 0.0f);
            atomicMin(&g_colMin[b * MM + j0 + tid], __float_as_uint(m));
        }
    }

    // ---- row mins: reduce across tx, write once (no atomic needed) ----
    __syncthreads();
    #pragma unroll
    for (int r = 0; r < 8; r++)
        red[tx * 128 + ty * 8 + r] = rm[r];
    __syncthreads();
    if (tid < 128) {
        float m = finf();
        #pragma unroll
        for (int t = 0; t < 16; t++)
            m = fminf(m, red[t * 128 + tid]);
        m = fmaxf(m, 0.0f);
        g_rowMin[b * NN + i0 + tid] = __float_as_uint(m);
    }
}

// ---------------------------------------------------------------------------
// Kernel 3a/3b: deterministic sum of sqrt(min) -> scalar
// ---------------------------------------------------------------------------
__global__ void reduce1_kernel() {
    __shared__ float s[256];
    const int tid  = threadIdx.x;
    const int base = blockIdx.x * 512;
    float v = 0.0f;
    #pragma unroll
    for (int o = 0; o < 512; o += 256) {
        int idx = base + o + tid;                 // 0 .. 131071
        unsigned u = (idx < BB * NN) ? g_rowMin[idx]
                                     : g_colMin[idx - BB * NN];
        v += sqrtf(__uint_as_float(u));
    }
    s[tid] = v;
    __syncthreads();
    for (int st = 128; st > 0; st >>= 1) {
        if (tid < st) s[tid] += s[tid + st];
        __syncthreads();
    }
    if (tid == 0) g_partial[blockIdx.x] = s[0];
}

__global__ void reduce2_kernel(float* __restrict__ out) {
    __shared__ float s[256];
    const int tid = threadIdx.x;
    s[tid] = g_partial[tid];
    __syncthreads();
    for (int st = 128; st > 0; st >>= 1) {
        if (tid < st) s[tid] += s[tid + st];
        __syncthreads();
    }
    if (tid == 0) out[0] = s[0];
}

// ---------------------------------------------------------------------------
extern "C" void kernel_launch(void* const* d_in, const int* in_sizes, int n_in,
                              void* d_out, int out_size) {
    const float* x = (const float*)d_in[0];
    const float* y = (const float*)d_in[1];
    float* out = (float*)d_out;

    init_mins_kernel<<<256, 256>>>();                       // 65536 threads
    sqnorm_kernel<<<(2 * BB * NN * 32) / 256, 256>>>(x, y); // 131072 warps
    chamfer_main_kernel<<<dim3(NN / TI, BB), 256>>>(x, y);
    reduce1_kernel<<<256, 256>>>();
    reduce2_kernel<<<1, 256>>>(out);
}

// round 3
// speedup vs baseline: 3.5620x; 3.5620x over previous
#include <cuda_runtime.h>
#include <cstdint>

#define BB 32
#define NN 2048
#define MM 2048
#define DD 128

#define NJT 16            // j-tiles per CTA

// smem float offsets
#define XS_OFF 0
#define Y0_OFF 16896      // 128*132
#define Y1_OFF 33792
#define YN_OFF 50688      // 2048 floats
#define XN_OFF 52736      // 128 floats
#define SM_FLOATS 52864
#define SM_BYTES (SM_FLOATS * 4)

// Scratch
__device__ float        g_xn[BB * NN];
__device__ float        g_yn[BB * MM];
__device__ unsigned int g_rowMin[BB * NN];
__device__ unsigned int g_colMin[BB * MM];
__device__ float        g_partial[256];

__device__ __forceinline__ float finf() { return __int_as_float(0x7f800000); }

__device__ __forceinline__ uint32_t smem_u32(const void* p) {
    uint32_t a;
    asm("{ .reg .u64 t; cvta.to.shared.u64 t, %1; cvt.u32.u64 %0, t; }" : "=r"(a) : "l"(p));
    return a;
}
__device__ __forceinline__ void cpasync16(uint32_t dst, const void* src) {
    asm volatile("cp.async.cg.shared.global [%0], [%1], 16;" :: "r"(dst), "l"(src) : "memory");
}
__device__ __forceinline__ void cpasync_commit() {
    asm volatile("cp.async.commit_group;" ::: "memory");
}
__device__ __forceinline__ void cpasync_wait_all() {
    asm volatile("cp.async.wait_all;" ::: "memory");
}
__device__ __forceinline__ void cpasync_wait0() {
    asm volatile("cp.async.wait_group 0;" ::: "memory");
}

__device__ __forceinline__ void mma_tf32(float* c, const uint32_t* a, const uint32_t* b) {
    asm volatile(
        "mma.sync.aligned.m16n8k8.row.col.f32.tf32.tf32.f32 "
        "{%0,%1,%2,%3}, {%4,%5,%6,%7}, {%8,%9}, {%0,%1,%2,%3};"
        : "+f"(c[0]), "+f"(c[1]), "+f"(c[2]), "+f"(c[3])
        : "r"(a[0]), "r"(a[1]), "r"(a[2]), "r"(a[3]), "r"(b[0]), "r"(b[1]));
}

// ---------------------------------------------------------------------------
__global__ void init_mins_kernel() {
    int i = blockIdx.x * blockDim.x + threadIdx.x;
    if (i < BB * NN) g_rowMin[i] = 0x7f800000u;
    if (i < BB * MM) g_colMin[i] = 0x7f800000u;
}

__global__ void sqnorm_kernel(const float* __restrict__ x,
                              const float* __restrict__ y) {
    int w    = (blockIdx.x * blockDim.x + threadIdx.x) >> 5;
    int lane = threadIdx.x & 31;
    const int rowsX = BB * NN;
    const float* src;
    float* dst;
    if (w < rowsX) { src = x + (size_t)w * DD; dst = &g_xn[w]; }
    else { int w2 = w - rowsX; src = y + (size_t)w2 * DD; dst = &g_yn[w2]; }
    float4 v = *(const float4*)(src + lane * 4);
    float s = v.x * v.x + v.y * v.y + v.z * v.z + v.w * v.w;
    #pragma unroll
    for (int off = 16; off > 0; off >>= 1)
        s += __shfl_xor_sync(0xffffffffu, s, off);
    if (lane == 0) *dst = s;
}

// ---------------------------------------------------------------------------
// Main: 256 thr, 8 warps (2M x 4N), warp tile 64x32, m16n8k8 tf32 mma.sync.
// ---------------------------------------------------------------------------
__device__ __forceinline__ void load_tile128(const float* __restrict__ g,
                                             uint32_t sbase_bytes, int tid) {
    // 128 rows x 128 floats -> smem rows padded to 132 floats
    #pragma unroll
    for (int p = 0; p < 16; p++) {
        int linear = p * 256 + tid;        // 0..4095 float4 chunks
        int row = linear >> 5;
        int f4  = linear & 31;
        cpasync16(sbase_bytes + (uint32_t)(row * 132 + f4 * 4) * 4,
                  g + (size_t)row * DD + f4 * 4);
    }
}

__global__ __launch_bounds__(256, 1)
void chamfer_mma_kernel(const float* __restrict__ x,
                        const float* __restrict__ y) {
    extern __shared__ float sm[];
    const uint32_t sb = smem_u32(sm);

    const int b    = blockIdx.y;
    const int i0   = blockIdx.x * 128;
    const int tid  = threadIdx.x;
    const int wid  = tid >> 5;
    const int lane = tid & 31;
    const int gq   = lane >> 2;      // 0..7
    const int t4   = lane & 3;       // 0..3
    const int wm   = wid & 1;        // 2 warps in M
    const int wn   = wid >> 1;       // 4 warps in N
    const int m0   = wm * 64;
    const int n0   = wn * 32;

    const float* xb = x + (size_t)b * NN * DD;
    const float* yb = y + (size_t)b * MM * DD;

    // ---- prologue loads ----
    load_tile128(xb + (size_t)i0 * DD, sb + XS_OFF * 4, tid);
    load_tile128(yb, sb + Y0_OFF * 4, tid);
    #pragma unroll
    for (int p = 0; p < 2; p++) {
        int idx = p * 256 + tid;   // 512 float4 = 2048 floats
        cpasync16(sb + (YN_OFF + idx * 4) * 4, g_yn + (size_t)b * MM + idx * 4);
    }
    if (tid < 32)
        cpasync16(sb + (XN_OFF + tid * 4) * 4, g_xn + (size_t)b * NN + i0 + tid * 4);
    cpasync_wait_all();
    __syncthreads();

    const float* Xs   = sm + XS_OFF;
    const float* yn_s = sm + YN_OFF;
    const float* xn_s = sm + XN_OFF;

    // xn for this thread's 8 rows
    float xnr[4][2];
    #pragma unroll
    for (int mt = 0; mt < 4; mt++) {
        xnr[mt][0] = xn_s[m0 + mt * 16 + gq];
        xnr[mt][1] = xn_s[m0 + mt * 16 + gq + 8];
    }

    float rmin[4][2];
    #pragma unroll
    for (int mt = 0; mt < 4; mt++) { rmin[mt][0] = finf(); rmin[mt][1] = finf(); }

    for (int t = 0; t < NJT; t++) {
        if (t > 0) { cpasync_wait0(); __syncthreads(); }
        // prefetch next Y tile
        if (t + 1 < NJT) {
            uint32_t buf = ((t + 1) & 1) ? Y1_OFF : Y0_OFF;
            load_tile128(yb + (size_t)(t + 1) * 128 * DD, sb + buf * 4, tid);
            cpasync_commit();
        }
        const float* Ys = sm + ((t & 1) ? Y1_OFF : Y0_OFF);

        float acc[4][4][4];
        #pragma unroll
        for (int mt = 0; mt < 4; mt++)
            #pragma unroll
            for (int nt = 0; nt < 4; nt++)
                #pragma unroll
                for (int e = 0; e < 4; e++) acc[mt][nt][e] = 0.0f;

        #pragma unroll
        for (int ks = 0; ks < 16; ks++) {
            const int k0 = ks * 8;
            uint32_t a[4][4], bf[4][2];
            #pragma unroll
            for (int mt = 0; mt < 4; mt++) {
                int r0 = m0 + mt * 16 + gq;
                a[mt][0] = __float_as_uint(Xs[r0 * 132 + k0 + t4]);
                a[mt][1] = __float_as_uint(Xs[(r0 + 8) * 132 + k0 + t4]);
                a[mt][2] = __float_as_uint(Xs[r0 * 132 + k0 + t4 + 4]);
                a[mt][3] = __float_as_uint(Xs[(r0 + 8) * 132 + k0 + t4 + 4]);
            }
            #pragma unroll
            for (int nt = 0; nt < 4; nt++) {
                int c0 = n0 + nt * 8 + gq;
                bf[nt][0] = __float_as_uint(Ys[c0 * 132 + k0 + t4]);
                bf[nt][1] = __float_as_uint(Ys[c0 * 132 + k0 + t4 + 4]);
            }
            #pragma unroll
            for (int mt = 0; mt < 4; mt++)
                #pragma unroll
                for (int nt = 0; nt < 4; nt++)
                    mma_tf32(acc[mt][nt], a[mt], bf[nt]);
        }

        // ---- epilogue: sq = xn + yn - 2*acc, fused min ----
        const int j0 = t * 128;
        float cmin[4][2];
        #pragma unroll
        for (int nt = 0; nt < 4; nt++) { cmin[nt][0] = finf(); cmin[nt][1] = finf(); }

        #pragma unroll
        for (int nt = 0; nt < 4; nt++) {
            float yc0 = yn_s[j0 + n0 + nt * 8 + 2 * t4];
            float yc1 = yn_s[j0 + n0 + nt * 8 + 2 * t4 + 1];
            #pragma unroll
            for (int mt = 0; mt < 4; mt++) {
                float s0 = fmaf(-2.0f, acc[mt][nt][0], xnr[mt][0] + yc0);
                float s1 = fmaf(-2.0f, acc[mt][nt][1], xnr[mt][0] + yc1);
                float s2 = fmaf(-2.0f, acc[mt][nt][2], xnr[mt][1] + yc0);
                float s3 = fmaf(-2.0f, acc[mt][nt][3], xnr[mt][1] + yc1);
                rmin[mt][0] = fminf(rmin[mt][0], fminf(s0, s1));
                rmin[mt][1] = fminf(rmin[mt][1], fminf(s2, s3));
                cmin[nt][0] = fminf(cmin[nt][0], fminf(s0, s2));
                cmin[nt][1] = fminf(cmin[nt][1], fminf(s1, s3));
            }
        }

        // col-min: reduce across g (lane bits 2..4), then atomicMin
        #pragma unroll
        for (int nt = 0; nt < 4; nt++)
            #pragma unroll
            for (int e = 0; e < 2; e++) {
                float v = cmin[nt][e];
                v = fminf(v, __shfl_xor_sync(0xffffffffu, v, 4));
                v = fminf(v, __shfl_xor_sync(0xffffffffu, v, 8));
                v = fminf(v, __shfl_xor_sync(0xffffffffu, v, 16));
                if (gq == 0) {
                    int col = j0 + n0 + nt * 8 + 2 * t4 + e;
                    atomicMin(&g_colMin[(size_t)b * MM + col],
                              __float_as_uint(fmaxf(v, 0.0f)));
                }
            }
    }

    // row-min: reduce across t4 (lane bits 0..1), then atomicMin
    #pragma unroll
    for (int mt = 0; mt < 4; mt++)
        #pragma unroll
        for (int e = 0; e < 2; e++) {
            float v = rmin[mt][e];
            v = fminf(v, __shfl_xor_sync(0xffffffffu, v, 1));
            v = fminf(v, __shfl_xor_sync(0xffffffffu, v, 2));
            if (t4 == 0) {
                int row = i0 + m0 + mt * 16 + gq + e * 8;
                atomicMin(&g_rowMin[(size_t)b * NN + row],
                          __float_as_uint(fmaxf(v, 0.0f)));
            }
        }
}

// ---------------------------------------------------------------------------
__global__ void reduce1_kernel() {
    __shared__ float s[256];
    const int tid  = threadIdx.x;
    const int base = blockIdx.x * 512;
    float v = 0.0f;
    #pragma unroll
    for (int o = 0; o < 512; o += 256) {
        int idx = base + o + tid;
        unsigned u = (idx < BB * NN) ? g_rowMin[idx] : g_colMin[idx - BB * NN];
        v += sqrtf(__uint_as_float(u));
    }
    s[tid] = v;
    __syncthreads();
    for (int st = 128; st > 0; st >>= 1) {
        if (tid < st) s[tid] += s[tid + st];
        __syncthreads();
    }
    if (tid == 0) g_partial[blockIdx.x] = s[0];
}

__global__ void reduce2_kernel(float* __restrict__ out) {
    __shared__ float s[256];
    const int tid = threadIdx.x;
    s[tid] = g_partial[tid];
    __syncthreads();
    for (int st = 128; st > 0; st >>= 1) {
        if (tid < st) s[tid] += s[tid + st];
        __syncthreads();
    }
    if (tid == 0) out[0] = s[0];
}

// ---------------------------------------------------------------------------
extern "C" void kernel_launch(void* const* d_in, const int* in_sizes, int n_in,
                              void* d_out, int out_size) {
    const float* x = (const float*)d_in[0];
    const float* y = (const float*)d_in[1];
    float* out = (float*)d_out;

    cudaFuncSetAttribute(chamfer_mma_kernel,
                         cudaFuncAttributeMaxDynamicSharedMemorySize, SM_BYTES);

    init_mins_kernel<<<256, 256>>>();
    sqnorm_kernel<<<(2 * BB * NN * 32) / 256, 256>>>(x, y);
    chamfer_mma_kernel<<<dim3(NN / 128, BB), 256, SM_BYTES>>>(x, y);
    reduce1_kernel<<<256, 256>>>();
    reduce2_kernel<<<1, 256>>>(out);
}

// round 5
// speedup vs baseline: 5.0103x; 1.4066x over previous
#include <cuda_runtime.h>
#include <cuda_fp16.h>
#include <cstdint>

#define BB 32
#define NN 2048
#define MM 2048
#define DD 128

#define NJT 16

// fp16 tiles in smem: 128 rows x 128 halfs, row stride 272 bytes (16B pad)
#define TROWB 272
#define TILEB (128 * TROWB)          // 34816
#define XS_B  0
#define Y0_B  TILEB
#define Y1_B  (2 * TILEB)
#define YN_B  (3 * TILEB)            // 104448, 2048 floats
#define XN_B  (YN_B + 8192)          // 112640, 128 floats
#define SM_BYTES (XN_B + 512)        // 113152

// Scratch
__device__ __half       g_xh[BB * NN * DD];   // 16 MB
__device__ __half       g_yh[BB * MM * DD];   // 16 MB
__device__ float        g_xn[BB * NN];
__device__ float        g_yn[BB * MM];
__device__ unsigned int g_rowMin[BB * NN];
__device__ unsigned int g_colMin[BB * MM];
__device__ float        g_partial[256];

__device__ __forceinline__ float finf() { return __int_as_float(0x7f800000); }

__device__ __forceinline__ uint32_t smem_u32(const void* p) {
    uint32_t a;
    asm("{ .reg .u64 t; cvta.to.shared.u64 t, %1; cvt.u32.u64 %0, t; }" : "=r"(a) : "l"(p));
    return a;
}
__device__ __forceinline__ void cpasync16(uint32_t dst, const void* src) {
    asm volatile("cp.async.cg.shared.global [%0], [%1], 16;" :: "r"(dst), "l"(src) : "memory");
}
__device__ __forceinline__ void cpasync_commit() {
    asm volatile("cp.async.commit_group;" ::: "memory");
}
__device__ __forceinline__ void cpasync_wait_all() {
    asm volatile("cp.async.wait_all;" ::: "memory");
}
__device__ __forceinline__ void cpasync_wait0() {
    asm volatile("cp.async.wait_group 0;" ::: "memory");
}
__device__ __forceinline__ void ldsm_x4(uint32_t* r, uint32_t addr) {
    asm volatile("ldmatrix.sync.aligned.m8n8.x4.shared.b16 {%0,%1,%2,%3}, [%4];"
                 : "=r"(r[0]), "=r"(r[1]), "=r"(r[2]), "=r"(r[3]) : "r"(addr));
}
__device__ __forceinline__ void mma_f16(float* c, const uint32_t* a,
                                        uint32_t b0, uint32_t b1) {
    asm volatile(
        "mma.sync.aligned.m16n8k16.row.col.f32.f16.f16.f32 "
        "{%0,%1,%2,%3}, {%4,%5,%6,%7}, {%8,%9}, {%0,%1,%2,%3};"
        : "+f"(c[0]), "+f"(c[1]), "+f"(c[2]), "+f"(c[3])
        : "r"(a[0]), "r"(a[1]), "r"(a[2]), "r"(a[3]), "r"(b0), "r"(b1));
}

// ---------------------------------------------------------------------------
__global__ void init_mins_kernel() {
    int i = blockIdx.x * blockDim.x + threadIdx.x;
    if (i < BB * NN) g_rowMin[i] = 0x7f800000u;
    if (i < BB * MM) g_colMin[i] = 0x7f800000u;
}

// Fused fp32->fp16 convert + squared norm. One warp per row.
__global__ void conv_norm_kernel(const float* __restrict__ x,
                                 const float* __restrict__ y) {
    int w    = (blockIdx.x * blockDim.x + threadIdx.x) >> 5;
    int lane = threadIdx.x & 31;
    const int rowsX = BB * NN;
    const float* src;
    __half* hdst;
    float* ndst;
    if (w < rowsX) { src = x + (size_t)w * DD; hdst = g_xh + (size_t)w * DD; ndst = &g_xn[w]; }
    else { int w2 = w - rowsX; src = y + (size_t)w2 * DD; hdst = g_yh + (size_t)w2 * DD; ndst = &g_yn[w2]; }

    float4 v = *(const float4*)(src + lane * 4);
    __half2 h0 = __floats2half2_rn(v.x, v.y);
    __half2 h1 = __floats2half2_rn(v.z, v.w);
    uint2 u;
    u.x = *reinterpret_cast<uint32_t*>(&h0);
    u.y = *reinterpret_cast<uint32_t*>(&h1);
    ((uint2*)hdst)[lane] = u;

    float s = v.x * v.x + v.y * v.y + v.z * v.z + v.w * v.w;
    #pragma unroll
    for (int off = 16; off > 0; off >>= 1)
        s += __shfl_xor_sync(0xffffffffu, s, off);
    if (lane == 0) *ndst = s;
}

// ---------------------------------------------------------------------------
// Main: 512 thr, 16 warps (4M x 4N), warp tile 32x32, m16n8k16 f16 mma.
// ---------------------------------------------------------------------------
__device__ __forceinline__ void load_tile_h(const __half* __restrict__ g,
                                            uint32_t sbase, int tid) {
    // 128 rows x 256 B -> smem rows at stride 272 B. 2048 16B chunks / 512 thr.
    #pragma unroll
    for (int p = 0; p < 4; p++) {
        int c   = p * 512 + tid;
        int row = c >> 4;
        int ch  = c & 15;
        cpasync16(sbase + (uint32_t)(row * TROWB + ch * 16),
                  g + (size_t)row * DD + ch * 8);
    }
}

__global__ __launch_bounds__(512, 1)
void chamfer_mma_kernel() {
    extern __shared__ char sm[];
    const uint32_t sb = smem_u32(sm);

    const int b    = blockIdx.y;
    const int i0   = blockIdx.x * 128;
    const int tid  = threadIdx.x;
    const int wid  = tid >> 5;
    const int lane = tid & 31;
    const int gq   = lane >> 2;
    const int t4   = lane & 3;
    const int wm   = wid & 3;        // 4 warps in M
    const int wn   = wid >> 2;       // 4 warps in N
    const int m0   = wm * 32;
    const int n0   = wn * 32;

    // ldmatrix per-lane row/k offsets (tile order: a0,a1,a2,a3)
    const int lm_row = ((lane >> 3) & 1) * 8 + (lane & 7);
    const int lm_k   = (lane >> 4) * 8;

    const __half* xb = g_xh + (size_t)b * NN * DD;
    const __half* yb = g_yh + (size_t)b * MM * DD;

    // ---- prologue ----
    load_tile_h(xb + (size_t)i0 * DD, sb + XS_B, tid);
    load_tile_h(yb, sb + Y0_B, tid);
    cpasync16(sb + YN_B + tid * 16, g_yn + (size_t)b * MM + tid * 4);  // 512*16B = 8KB
    if (tid < 32)
        cpasync16(sb + XN_B + tid * 16, g_xn + (size_t)b * NN + i0 + tid * 4);
    cpasync_wait_all();
    __syncthreads();

    const float* yn_s = (const float*)(sm + YN_B);
    const float* xn_s = (const float*)(sm + XN_B);

    float xnr[2][2];
    #pragma unroll
    for (int mt = 0; mt < 2; mt++) {
        xnr[mt][0] = xn_s[m0 + mt * 16 + gq];
        xnr[mt][1] = xn_s[m0 + mt * 16 + gq + 8];
    }
    float rmin[2][2];
    rmin[0][0] = rmin[0][1] = rmin[1][0] = rmin[1][1] = finf();

    for (int t = 0; t < NJT; t++) {
        if (t > 0) { cpasync_wait0(); __syncthreads(); }
        if (t + 1 < NJT) {
            uint32_t buf = ((t + 1) & 1) ? Y1_B : Y0_B;
            load_tile_h(yb + (size_t)(t + 1) * 128 * DD, sb + buf, tid);
            cpasync_commit();
        }
        const uint32_t Ysb = sb + ((t & 1) ? Y1_B : Y0_B);
        const uint32_t Xsb = sb + XS_B;

        float acc[2][4][4];
        #pragma unroll
        for (int mt = 0; mt < 2; mt++)
            #pragma unroll
            for (int nt = 0; nt < 4; nt++)
                #pragma unroll
                for (int e = 0; e < 4; e++) acc[mt][nt][e] = 0.0f;

        #pragma unroll
        for (int ks = 0; ks < 8; ks++) {
            const int k0 = ks * 16;
            uint32_t a[2][4], bfr[2][4];
            #pragma unroll
            for (int mt = 0; mt < 2; mt++)
                ldsm_x4(a[mt], Xsb + (uint32_t)((m0 + mt * 16 + lm_row) * TROWB
                                                + (k0 + lm_k) * 2));
            #pragma unroll
            for (int bh = 0; bh < 2; bh++)
                ldsm_x4(bfr[bh], Ysb + (uint32_t)((n0 + bh * 16 + lm_row) * TROWB
                                                  + (k0 + lm_k) * 2));
            #pragma unroll
            for (int mt = 0; mt < 2; mt++)
                #pragma unroll
                for (int nt = 0; nt < 4; nt++)
                    mma_f16(acc[mt][nt], a[mt], bfr[nt >> 1][nt & 1],
                            bfr[nt >> 1][(nt & 1) + 2]);
        }

        // ---- epilogue: sq = xn + yn - 2*acc, fused min ----
        const int j0 = t * 128;
        float cmin[4][2];
        #pragma unroll
        for (int nt = 0; nt < 4; nt++) { cmin[nt][0] = finf(); cmin[nt][1] = finf(); }

        #pragma unroll
        for (int nt = 0; nt < 4; nt++) {
            float yc0 = yn_s[j0 + n0 + nt * 8 + 2 * t4];
            float yc1 = yn_s[j0 + n0 + nt * 8 + 2 * t4 + 1];
            #pragma unroll
            for (int mt = 0; mt < 2; mt++) {
                float s0 = fmaf(-2.0f, acc[mt][nt][0], xnr[mt][0] + yc0);
                float s1 = fmaf(-2.0f, acc[mt][nt][1], xnr[mt][0] + yc1);
                float s2 = fmaf(-2.0f, acc[mt][nt][2], xnr[mt][1] + yc0);
                float s3 = fmaf(-2.0f, acc[mt][nt][3], xnr[mt][1] + yc1);
                rmin[mt][0] = fminf(rmin[mt][0], fminf(s0, s1));
                rmin[mt][1] = fminf(rmin[mt][1], fminf(s2, s3));
                cmin[nt][0] = fminf(cmin[nt][0], fminf(s0, s2));
                cmin[nt][1] = fminf(cmin[nt][1], fminf(s1, s3));
            }
        }

        #pragma unroll
        for (int nt = 0; nt < 4; nt++)
            #pragma unroll
            for (int e = 0; e < 2; e++) {
                float v = cmin[nt][e];
                v = fminf(v, __shfl_xor_sync(0xffffffffu, v, 4));
                v = fminf(v, __shfl_xor_sync(0xffffffffu, v, 8));
                v = fminf(v, __shfl_xor_sync(0xffffffffu, v, 16));
                if (gq == 0) {
                    int col = j0 + n0 + nt * 8 + 2 * t4 + e;
                    atomicMin(&g_colMin[(size_t)b * MM + col],
                              __float_as_uint(fmaxf(v, 0.0f)));
                }
            }
    }

    #pragma unroll
    for (int mt = 0; mt < 2; mt++)
        #pragma unroll
        for (int e = 0; e < 2; e++) {
            float v = rmin[mt][e];
            v = fminf(v, __shfl_xor_sync(0xffffffffu, v, 1));
            v = fminf(v, __shfl_xor_sync(0xffffffffu, v, 2));
            if (t4 == 0) {
                int row = i0 + m0 + mt * 16 + gq + e * 8;
                atomicMin(&g_rowMin[(size_t)b * NN + row],
                          __float_as_uint(fmaxf(v, 0.0f)));
            }
        }
}

// ---------------------------------------------------------------------------
__global__ void reduce1_kernel() {
    __shared__ float s[256];
    const int tid  = threadIdx.x;
    const int base = blockIdx.x * 512;
    float v = 0.0f;
    #pragma unroll
    for (int o = 0; o < 512; o += 256) {
        int idx = base + o + tid;
        unsigned u = (idx < BB * NN) ? g_rowMin[idx] : g_colMin[idx - BB * NN];
        v += sqrtf(__uint_as_float(u));
    }
    s[tid] = v;
    __syncthreads();
    for (int st = 128; st > 0; st >>= 1) {
        if (tid < st) s[tid] += s[tid + st];
        __syncthreads();
    }
    if (tid == 0) g_partial[blockIdx.x] = s[0];
}

__global__ void reduce2_kernel(float* __restrict__ out) {
    __shared__ float s[256];
    const int tid = threadIdx.x;
    s[tid] = g_partial[tid];
    __syncthreads();
    for (int st = 128; st > 0; st >>= 1) {
        if (tid < st) s[tid] += s[tid + st];
        __syncthreads();
    }
    if (tid == 0) out[0] = s[0];
}

// ---------------------------------------------------------------------------
extern "C" void kernel_launch(void* const* d_in, const int* in_sizes, int n_in,
                              void* d_out, int out_size) {
    const float* x = (const float*)d_in[0];
    const float* y = (const float*)d_in[1];
    float* out = (float*)d_out;

    cudaFuncSetAttribute(chamfer_mma_kernel,
                         cudaFuncAttributeMaxDynamicSharedMemorySize, SM_BYTES);

    init_mins_kernel<<<256, 256>>>();
    conv_norm_kernel<<<(2 * BB * NN * 32) / 256, 256>>>(x, y);
    chamfer_mma_kernel<<<dim3(NN / 128, BB), 512, SM_BYTES>>>();
    reduce1_kernel<<<256, 256>>>();
    reduce2_kernel<<<1, 256>>>(out);
}

// round 8
// speedup vs baseline: 5.0688x; 1.0117x over previous
#include <cuda_runtime.h>
#include <cuda_fp16.h>
#include <cstdint>

#define BB 32
#define NN 2048
#define MM 2048
#define DD 128

#define NJT 16

// fp16 tiles in smem: 128 rows x 128 halfs, row stride 272 bytes (16B pad)
#define TROWB 272
#define TILEB (128 * TROWB)          // 34816
#define XS_B  0
#define Y0_B  TILEB
#define Y1_B  (2 * TILEB)
#define YN_B  (3 * TILEB)            // 104448, 2048 floats
#define XN_B  (YN_B + 8192)          // 112640, 128 floats
#define SM_BYTES (XN_B + 512)        // 113152

// Scratch
__device__ __half       g_xh[BB * NN * DD];   // 16 MB
__device__ __half       g_yh[BB * MM * DD];   // 16 MB
__device__ float        g_xn[BB * NN];
__device__ float        g_yn[BB * MM];
__device__ unsigned int g_rowMin[BB * NN];
__device__ unsigned int g_colMin[BB * MM];
__device__ float        g_partial[256];

__device__ __forceinline__ float finf() { return __int_as_float(0x7f800000); }

__device__ __forceinline__ uint32_t smem_u32(const void* p) {
    uint32_t a;
    asm("{ .reg .u64 t; cvta.to.shared.u64 t, %1; cvt.u32.u64 %0, t; }" : "=r"(a) : "l"(p));
    return a;
}
__device__ __forceinline__ void cpasync16(uint32_t dst, const void* src) {
    asm volatile("cp.async.cg.shared.global [%0], [%1], 16;" :: "r"(dst), "l"(src) : "memory");
}
__device__ __forceinline__ void cpasync_commit() {
    asm volatile("cp.async.commit_group;" ::: "memory");
}
__device__ __forceinline__ void cpasync_wait_all() {
    asm volatile("cp.async.wait_all;" ::: "memory");
}
__device__ __forceinline__ void cpasync_wait0() {
    asm volatile("cp.async.wait_group 0;" ::: "memory");
}
__device__ __forceinline__ void ldsm_x4(uint32_t* r, uint32_t addr) {
    asm volatile("ldmatrix.sync.aligned.m8n8.x4.shared.b16 {%0,%1,%2,%3}, [%4];"
                 : "=r"(r[0]), "=r"(r[1]), "=r"(r[2]), "=r"(r[3]) : "r"(addr));
}
__device__ __forceinline__ void mma_f16(float* c, const uint32_t* a,
                                        uint32_t b0, uint32_t b1) {
    asm volatile(
        "mma.sync.aligned.m16n8k16.row.col.f32.f16.f16.f32 "
        "{%0,%1,%2,%3}, {%4,%5,%6,%7}, {%8,%9}, {%0,%1,%2,%3};"
        : "+f"(c[0]), "+f"(c[1]), "+f"(c[2]), "+f"(c[3])
        : "r"(a[0]), "r"(a[1]), "r"(a[2]), "r"(a[3]), "r"(b0), "r"(b1));
}

// ---------------------------------------------------------------------------
// Fused fp32->fp16 convert + squared norm + min-init. One warp per row.
// ---------------------------------------------------------------------------
__global__ void conv_norm_kernel(const float* __restrict__ x,
                                 const float* __restrict__ y) {
    int w    = (blockIdx.x * blockDim.x + threadIdx.x) >> 5;
    int lane = threadIdx.x & 31;
    const int rowsX = BB * NN;
    const float* src;
    __half* hdst;
    float* ndst;
    unsigned int* mdst;
    if (w < rowsX) {
        src = x + (size_t)w * DD; hdst = g_xh + (size_t)w * DD;
        ndst = &g_xn[w]; mdst = &g_rowMin[w];
    } else {
        int w2 = w - rowsX;
        src = y + (size_t)w2 * DD; hdst = g_yh + (size_t)w2 * DD;
        ndst = &g_yn[w2]; mdst = &g_colMin[w2];
    }

    float4 v = *(const float4*)(src + lane * 4);
    __half2 h0 = __floats2half2_rn(v.x, v.y);
    __half2 h1 = __floats2half2_rn(v.z, v.w);
    uint2 u;
    u.x = *reinterpret_cast<uint32_t*>(&h0);
    u.y = *reinterpret_cast<uint32_t*>(&h1);
    ((uint2*)hdst)[lane] = u;

    float s = v.x * v.x + v.y * v.y + v.z * v.z + v.w * v.w;
    #pragma unroll
    for (int off = 16; off > 0; off >>= 1)
        s += __shfl_xor_sync(0xffffffffu, s, off);
    if (lane == 0) { *ndst = s; *mdst = 0x7f800000u; }
}

// ---------------------------------------------------------------------------
// Main: 512 thr, 16 warps (4M x 4N), warp tile 32x32, m16n8k16 f16 mma.
// Fragment double-buffering across ks to hide LDSM latency.
// ---------------------------------------------------------------------------
__device__ __forceinline__ void load_tile_h(const __half* __restrict__ g,
                                            uint32_t sbase, int tid) {
    #pragma unroll
    for (int p = 0; p < 4; p++) {
        int c   = p * 512 + tid;
        int row = c >> 4;
        int ch  = c & 15;
        cpasync16(sbase + (uint32_t)(row * TROWB + ch * 16),
                  g + (size_t)row * DD + ch * 8);
    }
}

__global__ __launch_bounds__(512, 1)
void chamfer_mma_kernel() {
    extern __shared__ char sm[];
    const uint32_t sb = smem_u32(sm);

    const int b    = blockIdx.y;
    const int i0   = blockIdx.x * 128;
    const int tid  = threadIdx.x;
    const int wid  = tid >> 5;
    const int lane = tid & 31;
    const int gq   = lane >> 2;
    const int t4   = lane & 3;
    const int wm   = wid & 3;
    const int wn   = wid >> 2;
    const int m0   = wm * 32;
    const int n0   = wn * 32;

    const int lm_row = ((lane >> 3) & 1) * 8 + (lane & 7);
    const int lm_k   = (lane >> 4) * 8;

    const __half* xb = g_xh + (size_t)b * NN * DD;
    const __half* yb = g_yh + (size_t)b * MM * DD;

    // ---- prologue ----
    load_tile_h(xb + (size_t)i0 * DD, sb + XS_B, tid);
    load_tile_h(yb, sb + Y0_B, tid);
    cpasync16(sb + YN_B + tid * 16, g_yn + (size_t)b * MM + tid * 4);
    if (tid < 32)
        cpasync16(sb + XN_B + tid * 16, g_xn + (size_t)b * NN + i0 + tid * 4);
    cpasync_wait_all();
    __syncthreads();

    const float* yn_s = (const float*)(sm + YN_B);
    const float* xn_s = (const float*)(sm + XN_B);

    // precomputed fragment smem addresses (k advances by +32B per ks)
    const uint32_t a_addr0 = sb + XS_B + (uint32_t)((m0 + lm_row) * TROWB + lm_k * 2);
    const uint32_t a_addr1 = a_addr0 + 16 * TROWB;

    float xnr[2][2];
    #pragma unroll
    for (int mt = 0; mt < 2; mt++) {
        xnr[mt][0] = xn_s[m0 + mt * 16 + gq];
        xnr[mt][1] = xn_s[m0 + mt * 16 + gq + 8];
    }
    float rmin[2][2];
    rmin[0][0] = rmin[0][1] = rmin[1][0] = rmin[1][1] = finf();

    for (int t = 0; t < NJT; t++) {
        if (t > 0) { cpasync_wait0(); __syncthreads(); }
        if (t + 1 < NJT) {
            uint32_t buf = ((t + 1) & 1) ? Y1_B : Y0_B;
            load_tile_h(yb + (size_t)(t + 1) * 128 * DD, sb + buf, tid);
            cpasync_commit();
        }
        const uint32_t Ysb = sb + ((t & 1) ? Y1_B : Y0_B);
        const uint32_t b_addr0 = Ysb + (uint32_t)((n0 + lm_row) * TROWB + lm_k * 2);
        const uint32_t b_addr1 = b_addr0 + 16 * TROWB;

        float acc[2][4][4];
        #pragma unroll
        for (int mt = 0; mt < 2; mt++)
            #pragma unroll
            for (int nt = 0; nt < 4; nt++)
                #pragma unroll
                for (int e = 0; e < 4; e++) acc[mt][nt][e] = 0.0f;

        // fragment double buffers
        uint32_t a[2][2][4], bfr[2][2][4];
        ldsm_x4(a[0][0], a_addr0);
        ldsm_x4(a[0][1], a_addr1);
        ldsm_x4(bfr[0][0], b_addr0);
        ldsm_x4(bfr[0][1], b_addr1);

        #pragma unroll
        for (int ks = 0; ks < 8; ks++) {
            const int cur = ks & 1, nxt = cur ^ 1;
            if (ks < 7) {
                const uint32_t ko = (uint32_t)((ks + 1) * 32);
                ldsm_x4(a[nxt][0], a_addr0 + ko);
                ldsm_x4(a[nxt][1], a_addr1 + ko);
                ldsm_x4(bfr[nxt][0], b_addr0 + ko);
                ldsm_x4(bfr[nxt][1], b_addr1 + ko);
            }
            #pragma unroll
            for (int mt = 0; mt < 2; mt++)
                #pragma unroll
                for (int nt = 0; nt < 4; nt++)
                    mma_f16(acc[mt][nt], a[cur][mt], bfr[cur][nt >> 1][nt & 1],
                            bfr[cur][nt >> 1][(nt & 1) + 2]);
        }

        // ---- epilogue: sq = xn + yn - 2*acc, fused min ----
        const int j0 = t * 128;
        float cmin[4][2];
        #pragma unroll
        for (int nt = 0; nt < 4; nt++) { cmin[nt][0] = finf(); cmin[nt][1] = finf(); }

        #pragma unroll
        for (int nt = 0; nt < 4; nt++) {
            float yc0 = yn_s[j0 + n0 + nt * 8 + 2 * t4];
            float yc1 = yn_s[j0 + n0 + nt * 8 + 2 * t4 + 1];
            #pragma unroll
            for (int mt = 0; mt < 2; mt++) {
                float s0 = fmaf(-2.0f, acc[mt][nt][0], xnr[mt][0] + yc0);
                float s1 = fmaf(-2.0f, acc[mt][nt][1], xnr[mt][0] + yc1);
                float s2 = fmaf(-2.0f, acc[mt][nt][2], xnr[mt][1] + yc0);
                float s3 = fmaf(-2.0f, acc[mt][nt][3], xnr[mt][1] + yc1);
                rmin[mt][0] = fminf(rmin[mt][0], fminf(s0, s1));
                rmin[mt][1] = fminf(rmin[mt][1], fminf(s2, s3));
                cmin[nt][0] = fminf(cmin[nt][0], fminf(s0, s2));
                cmin[nt][1] = fminf(cmin[nt][1], fminf(s1, s3));
            }
        }

        #pragma unroll
        for (int nt = 0; nt < 4; nt++)
            #pragma unroll
            for (int e = 0; e < 2; e++) {
                float v = cmin[nt][e];
                v = fminf(v, __shfl_xor_sync(0xffffffffu, v, 4));
                v = fminf(v, __shfl_xor_sync(0xffffffffu, v, 8));
                v = fminf(v, __shfl_xor_sync(0xffffffffu, v, 16));
                if (gq == 0) {
                    int col = j0 + n0 + nt * 8 + 2 * t4 + e;
                    atomicMin(&g_colMin[(size_t)b * MM + col],
                              __float_as_uint(fmaxf(v, 0.0f)));
                }
            }
    }

    #pragma unroll
    for (int mt = 0; mt < 2; mt++)
        #pragma unroll
        for (int e = 0; e < 2; e++) {
            float v = rmin[mt][e];
            v = fminf(v, __shfl_xor_sync(0xffffffffu, v, 1));
            v = fminf(v, __shfl_xor_sync(0xffffffffu, v, 2));
            if (t4 == 0) {
                int row = i0 + m0 + mt * 16 + gq + e * 8;
                atomicMin(&g_rowMin[(size_t)b * NN + row],
                          __float_as_uint(fmaxf(v, 0.0f)));
            }
        }
}

// ---------------------------------------------------------------------------
__global__ void reduce1_kernel() {
    __shared__ float s[256];
    const int tid  = threadIdx.x;
    const int base = blockIdx.x * 512;
    float v = 0.0f;
    #pragma unroll
    for (int o = 0; o < 512; o += 256) {
        int idx = base + o + tid;
        unsigned u = (idx < BB * NN) ? g_rowMin[idx] : g_colMin[idx - BB * NN];
        v += sqrtf(__uint_as_float(u));
    }
    s[tid] = v;
    __syncthreads();
    for (int st = 128; st > 0; st >>= 1) {
        if (tid < st) s[tid] += s[tid + st];
        __syncthreads();
    }
    if (tid == 0) g_partial[blockIdx.x] = s[0];
}

__global__ void reduce2_kernel(float* __restrict__ out) {
    __shared__ float s[256];
    const int tid = threadIdx.x;
    s[tid] = g_partial[tid];
    __syncthreads();
    for (int st = 128; st > 0; st >>= 1) {
        if (tid < st) s[tid] += s[tid + st];
        __syncthreads();
    }
    if (tid == 0) out[0] = s[0];
}

// ---------------------------------------------------------------------------
extern "C" void kernel_launch(void* const* d_in, const int* in_sizes, int n_in,
                              void* d_out, int out_size) {
    const float* x = (const float*)d_in[0];
    const float* y = (const float*)d_in[1];
    float* out = (float*)d_out;

    cudaFuncSetAttribute(chamfer_mma_kernel,
                         cudaFuncAttributeMaxDynamicSharedMemorySize, SM_BYTES);

    // 4 launches/iter so ncu's skip-5/capture-1 lands on the main kernel.
    conv_norm_kernel<<<(2 * BB * NN * 32) / 256, 256>>>(x, y);
    chamfer_mma_kernel<<<dim3(NN / 128, BB), 512, SM_BYTES>>>();
    reduce1_kernel<<<256, 256>>>();
    reduce2_kernel<<<1, 256>>>(out);
}

// round 9
// speedup vs baseline: 5.4677x; 1.0787x over previous
#include <cuda_runtime.h>
#include <cuda_fp16.h>
#include <cstdint>

#define BB 32
#define NN 2048
#define MM 2048
#define DD 128

#define NJT 16

// fp16 tiles in smem: 128 rows x 128 halfs, row stride 272 bytes (16B pad)
#define TROWB 272
#define TILEB (128 * TROWB)          // 34816
#define XS_B  0
#define Y0_B  TILEB
#define Y1_B  (2 * TILEB)
#define YN_B  (3 * TILEB)            // 104448, 2048 floats
#define XN_B  (YN_B + 8192)          // 112640, 128 floats
#define SM_BYTES (XN_B + 512)        // 113152

// Scratch
__device__ __half       g_xh[BB * NN * DD];   // 16 MB
__device__ __half       g_yh[BB * MM * DD];   // 16 MB
__device__ float        g_xn[BB * NN];
__device__ float        g_yn[BB * MM];
__device__ unsigned int g_rowMin[BB * NN];
__device__ unsigned int g_colMin[BB * MM];
__device__ float        g_partial[256];

__device__ __forceinline__ float finf() { return __int_as_float(0x7f800000); }

__device__ __forceinline__ uint32_t smem_u32(const void* p) {
    uint32_t a;
    asm("{ .reg .u64 t; cvta.to.shared.u64 t, %1; cvt.u32.u64 %0, t; }" : "=r"(a) : "l"(p));
    return a;
}
__device__ __forceinline__ void cpasync16(uint32_t dst, const void* src) {
    asm volatile("cp.async.cg.shared.global [%0], [%1], 16;" :: "r"(dst), "l"(src) : "memory");
}
__device__ __forceinline__ void cpasync_commit() {
    asm volatile("cp.async.commit_group;" ::: "memory");
}
__device__ __forceinline__ void cpasync_wait_all() {
    asm volatile("cp.async.wait_all;" ::: "memory");
}
__device__ __forceinline__ void cpasync_wait0() {
    asm volatile("cp.async.wait_group 0;" ::: "memory");
}
__device__ __forceinline__ void ldsm_x4(uint32_t* r, uint32_t addr) {
    asm volatile("ldmatrix.sync.aligned.m8n8.x4.shared.b16 {%0,%1,%2,%3}, [%4];"
                 : "=r"(r[0]), "=r"(r[1]), "=r"(r[2]), "=r"(r[3]) : "r"(addr));
}
__device__ __forceinline__ void mma_f16(float* c, const uint32_t* a,
                                        uint32_t b0, uint32_t b1) {
    asm volatile(
        "mma.sync.aligned.m16n8k16.row.col.f32.f16.f16.f32 "
        "{%0,%1,%2,%3}, {%4,%5,%6,%7}, {%8,%9}, {%0,%1,%2,%3};"
        : "+f"(c[0]), "+f"(c[1]), "+f"(c[2]), "+f"(c[3])
        : "r"(a[0]), "r"(a[1]), "r"(a[2]), "r"(a[3]), "r"(b0), "r"(b1));
}

// ---------------------------------------------------------------------------
// Fused fp32->fp16 convert + squared norm + min-init. One warp per row.
// ---------------------------------------------------------------------------
__global__ void conv_norm_kernel(const float* __restrict__ x,
                                 const float* __restrict__ y) {
    int w    = (blockIdx.x * blockDim.x + threadIdx.x) >> 5;
    int lane = threadIdx.x & 31;
    const int rowsX = BB * NN;
    const float* src;
    __half* hdst;
    float* ndst;
    unsigned int* mdst;
    if (w < rowsX) {
        src = x + (size_t)w * DD; hdst = g_xh + (size_t)w * DD;
        ndst = &g_xn[w]; mdst = &g_rowMin[w];
    } else {
        int w2 = w - rowsX;
        src = y + (size_t)w2 * DD; hdst = g_yh + (size_t)w2 * DD;
        ndst = &g_yn[w2]; mdst = &g_colMin[w2];
    }

    float4 v = *(const float4*)(src + lane * 4);
    __half2 h0 = __floats2half2_rn(v.x, v.y);
    __half2 h1 = __floats2half2_rn(v.z, v.w);
    uint2 u;
    u.x = *reinterpret_cast<uint32_t*>(&h0);
    u.y = *reinterpret_cast<uint32_t*>(&h1);
    ((uint2*)hdst)[lane] = u;

    float s = v.x * v.x + v.y * v.y + v.z * v.z + v.w * v.w;
    #pragma unroll
    for (int off = 16; off > 0; off >>= 1)
        s += __shfl_xor_sync(0xffffffffu, s, off);
    if (lane == 0) { *ndst = s; *mdst = 0x7f800000u; }
}

// ---------------------------------------------------------------------------
// Main: 512 thr, 16 warps (4M x 4N), warp tile 32x32, m16n8k16 f16 mma.
// Accumulator double-buffering: epilogue of tile t-1 is interleaved into
// tile t's k-loop so fma/alu/shfl work hides under tensor-pipe execution.
// ---------------------------------------------------------------------------
__device__ __forceinline__ void load_tile_h(const __half* __restrict__ g,
                                            uint32_t sbase, int tid) {
    #pragma unroll
    for (int p = 0; p < 4; p++) {
        int c   = p * 512 + tid;
        int row = c >> 4;
        int ch  = c & 15;
        cpasync16(sbase + (uint32_t)(row * TROWB + ch * 16),
                  g + (size_t)row * DD + ch * 8);
    }
}

__global__ __launch_bounds__(512, 1)
void chamfer_mma_kernel() {
    extern __shared__ char sm[];
    const uint32_t sb = smem_u32(sm);

    const int b    = blockIdx.y;
    const int i0   = blockIdx.x * 128;
    const int tid  = threadIdx.x;
    const int wid  = tid >> 5;
    const int lane = tid & 31;
    const int gq   = lane >> 2;
    const int t4   = lane & 3;
    const int wm   = wid & 3;
    const int wn   = wid >> 2;
    const int m0   = wm * 32;
    const int n0   = wn * 32;

    const int lm_row = ((lane >> 3) & 1) * 8 + (lane & 7);
    const int lm_k   = (lane >> 4) * 8;

    const __half* xb = g_xh + (size_t)b * NN * DD;
    const __half* yb = g_yh + (size_t)b * MM * DD;

    // ---- prologue ----
    load_tile_h(xb + (size_t)i0 * DD, sb + XS_B, tid);
    load_tile_h(yb, sb + Y0_B, tid);
    cpasync16(sb + YN_B + tid * 16, g_yn + (size_t)b * MM + tid * 4);
    if (tid < 32)
        cpasync16(sb + XN_B + tid * 16, g_xn + (size_t)b * NN + i0 + tid * 4);
    cpasync_wait_all();
    __syncthreads();

    const float* yn_s = (const float*)(sm + YN_B);
    const float* xn_s = (const float*)(sm + XN_B);

    const uint32_t a_addr0 = sb + XS_B + (uint32_t)((m0 + lm_row) * TROWB + lm_k * 2);
    const uint32_t a_addr1 = a_addr0 + 16 * TROWB;

    float xnr[2][2];
    #pragma unroll
    for (int mt = 0; mt < 2; mt++) {
        xnr[mt][0] = xn_s[m0 + mt * 16 + gq];
        xnr[mt][1] = xn_s[m0 + mt * 16 + gq + 8];
    }
    float rmin[2][2];
    rmin[0][0] = rmin[0][1] = rmin[1][0] = rmin[1][1] = finf();

    float accA[2][4][4], accB[2][4][4];

    // 1/8th of the epilogue for a finished tile (chunk c = (nt, e))
    auto epi_chunk = [&](float (&accP)[2][4][4], int j0p, int c) {
        const int nt = c >> 1, e = c & 1;
        const int col = j0p + n0 + nt * 8 + 2 * t4 + e;
        float yc  = yn_s[col];
        float s00 = fmaf(-2.0f, accP[0][nt][e],     xnr[0][0] + yc);
        float s01 = fmaf(-2.0f, accP[0][nt][e + 2], xnr[0][1] + yc);
        float s10 = fmaf(-2.0f, accP[1][nt][e],     xnr[1][0] + yc);
        float s11 = fmaf(-2.0f, accP[1][nt][e + 2], xnr[1][1] + yc);
        rmin[0][0] = fminf(rmin[0][0], s00);
        rmin[0][1] = fminf(rmin[0][1], s01);
        rmin[1][0] = fminf(rmin[1][0], s10);
        rmin[1][1] = fminf(rmin[1][1], s11);
        float cmv = fminf(fminf(s00, s01), fminf(s10, s11));
        cmv = fminf(cmv, __shfl_xor_sync(0xffffffffu, cmv, 4));
        cmv = fminf(cmv, __shfl_xor_sync(0xffffffffu, cmv, 8));
        cmv = fminf(cmv, __shfl_xor_sync(0xffffffffu, cmv, 16));
        if (gq == 0)
            atomicMin(&g_colMin[(size_t)b * MM + col],
                      __float_as_uint(fmaxf(cmv, 0.0f)));
    };

    // one j-tile: MMAs into accC; interleaved epilogue chunks on accP (tile t-1)
    auto do_tile = [&](int t, float (&accC)[2][4][4], float (&accP)[2][4][4],
                       bool epi) {
        if (t > 0) { cpasync_wait0(); __syncthreads(); }
        if (t + 1 < NJT) {
            uint32_t buf = ((t + 1) & 1) ? Y1_B : Y0_B;
            load_tile_h(yb + (size_t)(t + 1) * 128 * DD, sb + buf, tid);
            cpasync_commit();
        }
        const uint32_t Ysb = sb + ((t & 1) ? Y1_B : Y0_B);
        const uint32_t b_addr0 = Ysb + (uint32_t)((n0 + lm_row) * TROWB + lm_k * 2);
        const uint32_t b_addr1 = b_addr0 + 16 * TROWB;

        #pragma unroll
        for (int mt = 0; mt < 2; mt++)
            #pragma unroll
            for (int nt = 0; nt < 4; nt++)
                #pragma unroll
                for (int e = 0; e < 4; e++) accC[mt][nt][e] = 0.0f;

        const int j0p = (t - 1) * 128;
        #pragma unroll
        for (int ks = 0; ks < 8; ks++) {
            const uint32_t ko = (uint32_t)(ks * 32);
            uint32_t a[2][4], bfr[2][4];
            ldsm_x4(a[0], a_addr0 + ko);
            ldsm_x4(a[1], a_addr1 + ko);
            ldsm_x4(bfr[0], b_addr0 + ko);
            ldsm_x4(bfr[1], b_addr1 + ko);
            #pragma unroll
            for (int mt = 0; mt < 2; mt++)
                #pragma unroll
                for (int nt = 0; nt < 4; nt++)
                    mma_f16(accC[mt][nt], a[mt], bfr[nt >> 1][nt & 1],
                            bfr[nt >> 1][(nt & 1) + 2]);
            if (epi) epi_chunk(accP, j0p, ks);
        }
    };

    for (int tt = 0; tt < NJT; tt += 2) {
        do_tile(tt,     accA, accB, tt > 0);
        do_tile(tt + 1, accB, accA, true);
    }
    // epilogue for the last tile (t = 15, accumulators in accB)
    #pragma unroll
    for (int c = 0; c < 8; c++) epi_chunk(accB, (NJT - 1) * 128, c);

    // ---- row-min flush ----
    #pragma unroll
    for (int mt = 0; mt < 2; mt++)
        #pragma unroll
        for (int e = 0; e < 2; e++) {
            float v = rmin[mt][e];
            v = fminf(v, __shfl_xor_sync(0xffffffffu, v, 1));
            v = fminf(v, __shfl_xor_sync(0xffffffffu, v, 2));
            if (t4 == 0) {
                int row = i0 + m0 + mt * 16 + gq + e * 8;
                atomicMin(&g_rowMin[(size_t)b * NN + row],
                          __float_as_uint(fmaxf(v, 0.0f)));
            }
        }
}

// ---------------------------------------------------------------------------
__global__ void reduce1_kernel() {
    __shared__ float s[256];
    const int tid  = threadIdx.x;
    const int base = blockIdx.x * 512;
    float v = 0.0f;
    #pragma unroll
    for (int o = 0; o < 512; o += 256) {
        int idx = base + o + tid;
        unsigned u = (idx < BB * NN) ? g_rowMin[idx] : g_colMin[idx - BB * NN];
        v += sqrtf(__uint_as_float(u));
    }
    s[tid] = v;
    __syncthreads();
    for (int st = 128; st > 0; st >>= 1) {
        if (tid < st) s[tid] += s[tid + st];
        __syncthreads();
    }
    if (tid == 0) g_partial[blockIdx.x] = s[0];
}

__global__ void reduce2_kernel(float* __restrict__ out) {
    __shared__ float s[256];
    const int tid = threadIdx.x;
    s[tid] = g_partial[tid];
    __syncthreads();
    for (int st = 128; st > 0; st >>= 1) {
        if (tid < st) s[tid] += s[tid + st];
        __syncthreads();
    }
    if (tid == 0) out[0] = s[0];
}

// ---------------------------------------------------------------------------
extern "C" void kernel_launch(void* const* d_in, const int* in_sizes, int n_in,
                              void* d_out, int out_size) {
    const float* x = (const float*)d_in[0];
    const float* y = (const float*)d_in[1];
    float* out = (float*)d_out;

    cudaFuncSetAttribute(chamfer_mma_kernel,
                         cudaFuncAttributeMaxDynamicSharedMemorySize, SM_BYTES);

    conv_norm_kernel<<<(2 * BB * NN * 32) / 256, 256>>>(x, y);
    chamfer_mma_kernel<<<dim3(NN / 128, BB), 512, SM_BYTES>>>();
    reduce1_kernel<<<256, 256>>>();
    reduce2_kernel<<<1, 256>>>(out);
}

// round 12
// speedup vs baseline: 5.8578x; 1.0714x over previous
#include <cuda_runtime.h>
#include <cuda_fp16.h>
#include <cstdint>

#define BB 32
#define NN 2048
#define MM 2048
#define DD 128

#define NJT_JOB 8         // j-tiles per job (half sweep)

// fp16 tiles in smem: 128 rows x 128 halfs, row stride 272 bytes (16B pad)
#define TROWB 272
#define TILEB (128 * TROWB)          // 34816
#define XS_B  0
#define Y0_B  TILEB
#define Y1_B  (2 * TILEB)
#define YN_B  (3 * TILEB)            // 104448, 2048 floats
#define XN_B  (YN_B + 8192)          // 112640, 128 floats
#define SM_BYTES (XN_B + 512)        // 113152

// Scratch
__device__ __half       g_xh[BB * NN * DD];   // 16 MB
__device__ __half       g_yh[BB * MM * DD];   // 16 MB
__device__ float        g_xn[BB * NN];
__device__ float        g_yn[BB * MM];
__device__ unsigned int g_rowMin[BB * NN];
__device__ unsigned int g_colMin[BB * MM];
__device__ float        g_partial[256];
__device__ unsigned int g_done = 0;

__device__ __forceinline__ float finf() { return __int_as_float(0x7f800000); }

__device__ __forceinline__ uint32_t smem_u32(const void* p) {
    uint32_t a;
    asm("{ .reg .u64 t; cvta.to.shared.u64 t, %1; cvt.u32.u64 %0, t; }" : "=r"(a) : "l"(p));
    return a;
}
__device__ __forceinline__ void cpasync16(uint32_t dst, const void* src) {
    asm volatile("cp.async.cg.shared.global [%0], [%1], 16;" :: "r"(dst), "l"(src) : "memory");
}
__device__ __forceinline__ void cpasync_commit() {
    asm volatile("cp.async.commit_group;" ::: "memory");
}
__device__ __forceinline__ void cpasync_wait_all() {
    asm volatile("cp.async.wait_all;" ::: "memory");
}
__device__ __forceinline__ void cpasync_wait0() {
    asm volatile("cp.async.wait_group 0;" ::: "memory");
}
__device__ __forceinline__ void ldsm_x4(uint32_t* r, uint32_t addr) {
    asm volatile("ldmatrix.sync.aligned.m8n8.x4.shared.b16 {%0,%1,%2,%3}, [%4];"
                 : "=r"(r[0]), "=r"(r[1]), "=r"(r[2]), "=r"(r[3]) : "r"(addr));
}
__device__ __forceinline__ void mma_f16(float* c, const uint32_t* a,
                                        uint32_t b0, uint32_t b1) {
    asm volatile(
        "mma.sync.aligned.m16n8k16.row.col.f32.f16.f16.f32 "
        "{%0,%1,%2,%3}, {%4,%5,%6,%7}, {%8,%9}, {%0,%1,%2,%3};"
        : "+f"(c[0]), "+f"(c[1]), "+f"(c[2]), "+f"(c[3])
        : "r"(a[0]), "r"(a[1]), "r"(a[2]), "r"(a[3]), "r"(b0), "r"(b1));
}

// ---------------------------------------------------------------------------
// Fused fp32->fp16 convert + squared norm + min-init. One warp per row.
// ---------------------------------------------------------------------------
__global__ void conv_norm_kernel(const float* __restrict__ x,
                                 const float* __restrict__ y) {
    int w    = (blockIdx.x * blockDim.x + threadIdx.x) >> 5;
    int lane = threadIdx.x & 31;
    const int rowsX = BB * NN;
    const float* src;
    __half* hdst;
    float* ndst;
    unsigned int* mdst;
    if (w < rowsX) {
        src = x + (size_t)w * DD; hdst = g_xh + (size_t)w * DD;
        ndst = &g_xn[w]; mdst = &g_rowMin[w];
    } else {
        int w2 = w - rowsX;
        src = y + (size_t)w2 * DD; hdst = g_yh + (size_t)w2 * DD;
        ndst = &g_yn[w2]; mdst = &g_colMin[w2];
    }

    float4 v = *(const float4*)(src + lane * 4);
    __half2 h0 = __floats2half2_rn(v.x, v.y);
    __half2 h1 = __floats2half2_rn(v.z, v.w);
    uint2 u;
    u.x = *reinterpret_cast<uint32_t*>(&h0);
    u.y = *reinterpret_cast<uint32_t*>(&h1);
    ((uint2*)hdst)[lane] = u;

    float s = v.x * v.x + v.y * v.y + v.z * v.z + v.w * v.w;
    #pragma unroll
    for (int off = 16; off > 0; off >>= 1)
        s += __shfl_xor_sync(0xffffffffu, s, off);
    if (lane == 0) { *ndst = s; *mdst = 0x7f800000u; }
}

// ---------------------------------------------------------------------------
// Main: 512 thr, 16 warps (4M x 4N), warp tile 32x32, m16n8k16 f16 mma.
// Job = (i-tile, batch, j-half): 1024 CTAs -> ~1% wave-quantization tail.
// Epilogue of tile t-1 interleaved into tile t's k-loop (acc double buffer).
// ---------------------------------------------------------------------------
__device__ __forceinline__ void load_tile_h(const __half* __restrict__ g,
                                            uint32_t sbase, int tid) {
    #pragma unroll
    for (int p = 0; p < 4; p++) {
        int c   = p * 512 + tid;
        int row = c >> 4;
        int ch  = c & 15;
        cpasync16(sbase + (uint32_t)(row * TROWB + ch * 16),
                  g + (size_t)row * DD + ch * 8);
    }
}

__global__ __launch_bounds__(512, 1)
void chamfer_mma_kernel() {
    extern __shared__ char sm[];
    const uint32_t sb = smem_u32(sm);

    const int b     = blockIdx.y;
    const int i0    = blockIdx.x * 128;
    const int jbase = blockIdx.z * NJT_JOB;   // first j-tile of this job
    const int tid  = threadIdx.x;
    const int lane = tid & 31;
    const int gq   = lane >> 2;
    const int t4   = lane & 3;
    const int wid  = tid >> 5;
    const int wm   = wid & 3;
    const int wn   = wid >> 2;
    const int m0   = wm * 32;
    const int n0   = wn * 32;

    const int lm_row = ((lane >> 3) & 1) * 8 + (lane & 7);
    const int lm_k   = (lane >> 4) * 8;

    const __half* xb = g_xh + (size_t)b * NN * DD;
    const __half* yb = g_yh + (size_t)b * MM * DD;

    // ---- prologue ----
    load_tile_h(xb + (size_t)i0 * DD, sb + XS_B, tid);
    load_tile_h(yb + (size_t)jbase * 128 * DD, sb + Y0_B, tid);
    cpasync16(sb + YN_B + tid * 16, g_yn + (size_t)b * MM + tid * 4);
    if (tid < 32)
        cpasync16(sb + XN_B + tid * 16, g_xn + (size_t)b * NN + i0 + tid * 4);
    cpasync_wait_all();
    __syncthreads();

    const float* yn_s = (const float*)(sm + YN_B);
    const float* xn_s = (const float*)(sm + XN_B);

    const uint32_t a_addr0 = sb + XS_B + (uint32_t)((m0 + lm_row) * TROWB + lm_k * 2);
    const uint32_t a_addr1 = a_addr0 + 16 * TROWB;

    float xnr[2][2];
    #pragma unroll
    for (int mt = 0; mt < 2; mt++) {
        xnr[mt][0] = xn_s[m0 + mt * 16 + gq];
        xnr[mt][1] = xn_s[m0 + mt * 16 + gq + 8];
    }
    float rmin[2][2];
    rmin[0][0] = rmin[0][1] = rmin[1][0] = rmin[1][1] = finf();

    float accA[2][4][4], accB[2][4][4];

    // 1/8th of the epilogue for a finished tile (chunk c = (nt, e)); j0p global
    auto epi_chunk = [&](float (&accP)[2][4][4], int j0p, int c) {
        const int nt = c >> 1, e = c & 1;
        const int col = j0p + n0 + nt * 8 + 2 * t4 + e;
        float yc  = yn_s[col];
        float s00 = fmaf(-2.0f, accP[0][nt][e],     xnr[0][0] + yc);
        float s01 = fmaf(-2.0f, accP[0][nt][e + 2], xnr[0][1] + yc);
        float s10 = fmaf(-2.0f, accP[1][nt][e],     xnr[1][0] + yc);
        float s11 = fmaf(-2.0f, accP[1][nt][e + 2], xnr[1][1] + yc);
        rmin[0][0] = fminf(rmin[0][0], s00);
        rmin[0][1] = fminf(rmin[0][1], s01);
        rmin[1][0] = fminf(rmin[1][0], s10);
        rmin[1][1] = fminf(rmin[1][1], s11);
        float cmv = fminf(fminf(s00, s01), fminf(s10, s11));
        cmv = fminf(cmv, __shfl_xor_sync(0xffffffffu, cmv, 4));
        cmv = fminf(cmv, __shfl_xor_sync(0xffffffffu, cmv, 8));
        cmv = fminf(cmv, __shfl_xor_sync(0xffffffffu, cmv, 16));
        if (gq == 0)
            atomicMin(&g_colMin[(size_t)b * MM + col],
                      __float_as_uint(fmaxf(cmv, 0.0f)));
    };

    // one local j-tile t (0..7): MMAs into accC; epilogue chunks on accP
    auto do_tile = [&](int t, float (&accC)[2][4][4], float (&accP)[2][4][4],
                       bool epi) {
        if (t > 0) { cpasync_wait0(); __syncthreads(); }
        if (t + 1 < NJT_JOB) {
            uint32_t buf = ((t + 1) & 1) ? Y1_B : Y0_B;
            load_tile_h(yb + (size_t)(jbase + t + 1) * 128 * DD, sb + buf, tid);
            cpasync_commit();
        }
        const uint32_t Ysb = sb + ((t & 1) ? Y1_B : Y0_B);
        const uint32_t b_addr0 = Ysb + (uint32_t)((n0 + lm_row) * TROWB + lm_k * 2);
        const uint32_t b_addr1 = b_addr0 + 16 * TROWB;

        #pragma unroll
        for (int mt = 0; mt < 2; mt++)
            #pragma unroll
            for (int nt = 0; nt < 4; nt++)
                #pragma unroll
                for (int e = 0; e < 4; e++) accC[mt][nt][e] = 0.0f;

        const int j0p = (jbase + t - 1) * 128;
        #pragma unroll
        for (int ks = 0; ks < 8; ks++) {
            const uint32_t ko = (uint32_t)(ks * 32);
            uint32_t a[2][4], bfr[2][4];
            ldsm_x4(a[0], a_addr0 + ko);
            ldsm_x4(a[1], a_addr1 + ko);
            ldsm_x4(bfr[0], b_addr0 + ko);
            ldsm_x4(bfr[1], b_addr1 + ko);
            #pragma unroll
            for (int mt = 0; mt < 2; mt++)
                #pragma unroll
                for (int nt = 0; nt < 4; nt++)
                    mma_f16(accC[mt][nt], a[mt], bfr[nt >> 1][nt & 1],
                            bfr[nt >> 1][(nt & 1) + 2]);
            if (epi) epi_chunk(accP, j0p, ks);
        }
    };

    for (int tt = 0; tt < NJT_JOB; tt += 2) {
        do_tile(tt,     accA, accB, tt > 0);
        do_tile(tt + 1, accB, accA, true);
    }
    // epilogue for the last tile (accumulators in accB)
    #pragma unroll
    for (int c = 0; c < 8; c++) epi_chunk(accB, (jbase + NJT_JOB - 1) * 128, c);

    // ---- row-min flush ----
    #pragma unroll
    for (int mt = 0; mt < 2; mt++)
        #pragma unroll
        for (int e = 0; e < 2; e++) {
            float v = rmin[mt][e];
            v = fminf(v, __shfl_xor_sync(0xffffffffu, v, 1));
            v = fminf(v, __shfl_xor_sync(0xffffffffu, v, 2));
            if (t4 == 0) {
                int row = i0 + m0 + mt * 16 + gq + e * 8;
                atomicMin(&g_rowMin[(size_t)b * NN + row],
                          __float_as_uint(fmaxf(v, 0.0f)));
            }
        }
}

// ---------------------------------------------------------------------------
// Fused two-stage reduce: 256 blocks, last block finishes (counter wraps to 0
// automatically via atomicInc, so the kernel is graph-replay safe).
// ---------------------------------------------------------------------------
__global__ void reduce_kernel(float* __restrict__ out) {
    __shared__ float s[256];
    __shared__ bool amLast;
    const int tid  = threadIdx.x;
    const int base = blockIdx.x * 512;
    float v = 0.0f;
    #pragma unroll
    for (int o = 0; o < 512; o += 256) {
        int idx = base + o + tid;
        unsigned u = (idx < BB * NN) ? g_rowMin[idx] : g_colMin[idx - BB * NN];
        v += sqrtf(__uint_as_float(u));
    }
    s[tid] = v;
    __syncthreads();
    for (int st = 128; st > 0; st >>= 1) {
        if (tid < st) s[tid] += s[tid + st];
        __syncthreads();
    }
    if (tid == 0) {
        g_partial[blockIdx.x] = s[0];
        __threadfence();
        unsigned prev = atomicInc(&g_done, gridDim.x - 1);
        amLast = (prev == gridDim.x - 1);
    }
    __syncthreads();
    if (amLast) {
        float p = ((volatile float*)g_partial)[tid];
        s[tid] = p;
        __syncthreads();
        for (int st = 128; st > 0; st >>= 1) {
            if (tid < st) s[tid] += s[tid + st];
            __syncthreads();
        }
        if (tid == 0) out[0] = s[0];
    }
}

// ---------------------------------------------------------------------------
extern "C" void kernel_launch(void* const* d_in, const int* in_sizes, int n_in,
                              void* d_out, int out_size) {
    const float* x = (const float*)d_in[0];
    const float* y = (const float*)d_in[1];
    float* out = (float*)d_out;

    cudaFuncSetAttribute(chamfer_mma_kernel,
                         cudaFuncAttributeMaxDynamicSharedMemorySize, SM_BYTES);

    conv_norm_kernel<<<(2 * BB * NN * 32) / 256, 256>>>(x, y);
    chamfer_mma_kernel<<<dim3(NN / 128, BB, 2), 512, SM_BYTES>>>();
    reduce_kernel<<<256, 256>>>(out);
}